// round 5
// baseline (speedup 1.0000x reference)
#include <cuda_runtime.h>
#include <cuda_bf16.h>
#include <math.h>
#include <stdint.h>

// Problem constants
constexpr int BATCH = 4;
constexpr int SEQ   = 2048;
constexpr int DIM   = 1024;
constexpr int NHEAD = 16;
constexpr int HDIM  = 64;
constexpr int NTOK  = BATCH * SEQ;   // 8192
constexpr int BHS   = BATCH * NHEAD; // 64

// ---------------------------------------------------------------------------
// Device scratch (no allocation allowed)
// ---------------------------------------------------------------------------
__device__ __align__(16) float g_q[BHS * SEQ * HDIM];   // fp32 post-proj Q [b,h,s,dk]
__device__ __align__(16) float g_k[BHS * SEQ * HDIM];   // fp32 post-proj K

// pre-split inputs (hi/lo bf16)
__device__ __align__(16) __nv_bfloat16 aqh[NTOK * DIM], aql[NTOK * DIM];
__device__ __align__(16) __nv_bfloat16 akh[NTOK * DIM], akl[NTOK * DIM];
__device__ __align__(16) __nv_bfloat16 avh[NTOK * DIM], avl[NTOK * DIM];
// pre-split weights
__device__ __align__(16) __nv_bfloat16 wqh[DIM * DIM], wql[DIM * DIM];
__device__ __align__(16) __nv_bfloat16 wkh[DIM * DIM], wkl[DIM * DIM];
__device__ __align__(16) __nv_bfloat16 wvh[DIM * DIM], wvl[DIM * DIM];
__device__ __align__(16) __nv_bfloat16 woh[DIM * DIM], wol[DIM * DIM];
// post-rope Q/K, post-proj V (hi/lo bf16, [b,h,s,dk])
__device__ __align__(16) __nv_bfloat16 qh_g[BHS * SEQ * HDIM], ql_g[BHS * SEQ * HDIM];
__device__ __align__(16) __nv_bfloat16 kh_g[BHS * SEQ * HDIM], kl_g[BHS * SEQ * HDIM];
__device__ __align__(16) __nv_bfloat16 vh_g[BHS * SEQ * HDIM], vl_g[BHS * SEQ * HDIM];
// attention output (hi/lo bf16, [b,s,d]) -> O-projection input
__device__ __align__(16) __nv_bfloat16 xh_g[NTOK * DIM], xl_g[NTOK * DIM];

// ---------------------------------------------------------------------------
// Helpers
// ---------------------------------------------------------------------------
__device__ __forceinline__ uint32_t smem_u32(const void* p) {
    uint32_t a;
    asm("{ .reg .u64 t; cvta.to.shared.u64 t, %1; cvt.u32.u64 %0, t; }"
        : "=r"(a) : "l"(p));
    return a;
}

__device__ __forceinline__ void cp16(uint32_t dst, const void* src) {
    asm volatile("cp.async.cg.shared.global [%0], [%1], 16;"
        :: "r"(dst), "l"(__cvta_generic_to_global(src)) : "memory");
}
#define CP_COMMIT() asm volatile("cp.async.commit_group;" ::: "memory")
template <int N>
__device__ __forceinline__ void cp_wait() {
    asm volatile("cp.async.wait_group %0;" :: "n"(N) : "memory");
}

__device__ __forceinline__ void ldm_x4(uint32_t* r, uint32_t addr) {
    asm volatile("ldmatrix.sync.aligned.m8n8.x4.shared.b16 {%0,%1,%2,%3}, [%4];"
        : "=r"(r[0]), "=r"(r[1]), "=r"(r[2]), "=r"(r[3]) : "r"(addr));
}
__device__ __forceinline__ void ldm_x4_t(uint32_t* r, uint32_t addr) {
    asm volatile("ldmatrix.sync.aligned.m8n8.x4.trans.shared.b16 {%0,%1,%2,%3}, [%4];"
        : "=r"(r[0]), "=r"(r[1]), "=r"(r[2]), "=r"(r[3]) : "r"(addr));
}
__device__ __forceinline__ void ldm_x2(uint32_t* r, uint32_t addr) {
    asm volatile("ldmatrix.sync.aligned.m8n8.x2.shared.b16 {%0,%1}, [%2];"
        : "=r"(r[0]), "=r"(r[1]) : "r"(addr));
}
__device__ __forceinline__ void mma16816(float* c, const uint32_t* a, const uint32_t* b) {
    asm volatile(
        "mma.sync.aligned.m16n8k16.row.col.f32.bf16.bf16.f32 "
        "{%0,%1,%2,%3}, {%4,%5,%6,%7}, {%8,%9}, {%0,%1,%2,%3};"
        : "+f"(c[0]), "+f"(c[1]), "+f"(c[2]), "+f"(c[3])
        : "r"(a[0]), "r"(a[1]), "r"(a[2]), "r"(a[3]), "r"(b[0]), "r"(b[1]));
}

__device__ __forceinline__ void cvt_hl(float4 v, uint2& hi, uint2& lo) {
    __nv_bfloat162 h0 = __floats2bfloat162_rn(v.x, v.y);
    __nv_bfloat162 h1 = __floats2bfloat162_rn(v.z, v.w);
    float2 f0 = __bfloat1622float2(h0);
    float2 f1 = __bfloat1622float2(h1);
    __nv_bfloat162 l0 = __floats2bfloat162_rn(v.x - f0.x, v.y - f0.y);
    __nv_bfloat162 l1 = __floats2bfloat162_rn(v.z - f1.x, v.w - f1.y);
    hi.x = *(uint32_t*)&h0; hi.y = *(uint32_t*)&h1;
    lo.x = *(uint32_t*)&l0; lo.y = *(uint32_t*)&l1;
}

__device__ __forceinline__ void pack_hl(float a, float b, uint32_t& hi, uint32_t& lo) {
    __nv_bfloat162 h = __floats2bfloat162_rn(a, b);
    float2 hf = __bfloat1622float2(h);
    __nv_bfloat162 l = __floats2bfloat162_rn(a - hf.x, b - hf.y);
    hi = *(uint32_t*)&h;
    lo = *(uint32_t*)&l;
}

// FFMA-only exp2 (no MUFU)
__device__ __forceinline__ float exp2fast(float y) {
    y = fmaxf(y, -80.0f);
    float t = y + 12582912.0f;
    float f = y - (t - 12582912.0f);
    float p = 0.0013333558f;
    p = fmaf(p, f, 0.0096181291f);
    p = fmaf(p, f, 0.0555041087f);
    p = fmaf(p, f, 0.2402265069f);
    p = fmaf(p, f, 0.6931471806f);
    p = fmaf(p, f, 1.0f);
    return __int_as_float(__float_as_int(p) + (__float_as_int(t) << 23));
}

// ---------------------------------------------------------------------------
// Pre-convert kernels: fp32 -> (hi, lo) bf16
// ---------------------------------------------------------------------------
__global__ void __launch_bounds__(256)
conv_inputs(const float* __restrict__ q, const float* __restrict__ k,
            const float* __restrict__ v)
{
    const int sel = blockIdx.z;
    const float* src = (sel == 0) ? q : (sel == 1) ? k : v;
    __nv_bfloat16* dh = (sel == 0) ? aqh : (sel == 1) ? akh : avh;
    __nv_bfloat16* dl = (sel == 0) ? aql : (sel == 1) ? akl : avl;
    const size_t i = ((size_t)blockIdx.x * 256 + threadIdx.x) * 4;
    float4 val = *(const float4*)(src + i);
    uint2 hi, lo;
    cvt_hl(val, hi, lo);
    *(uint2*)(dh + i) = hi;
    *(uint2*)(dl + i) = lo;
}

__global__ void __launch_bounds__(256)
conv_weights(const float* __restrict__ wq, const float* __restrict__ wk,
             const float* __restrict__ wv, const float* __restrict__ wo)
{
    const int sel = blockIdx.z;
    const float* src = (sel == 0) ? wq : (sel == 1) ? wk : (sel == 2) ? wv : wo;
    __nv_bfloat16* dh = (sel == 0) ? wqh : (sel == 1) ? wkh : (sel == 2) ? wvh : woh;
    __nv_bfloat16* dl = (sel == 0) ? wql : (sel == 1) ? wkl : (sel == 2) ? wvl : wol;
    const size_t i = ((size_t)blockIdx.x * 256 + threadIdx.x) * 4;
    float4 val = *(const float4*)(src + i);
    uint2 hi, lo;
    cvt_hl(val, hi, lo);
    *(uint2*)(dh + i) = hi;
    *(uint2*)(dl + i) = lo;
}

// ===========================================================================
// GEMM v2: C = A @ W^T, pre-split bf16 inputs, cp.async double-buffered.
// Tile 128x128, K-stage 32, 8 warps (2M x 4N).
// MODE 0: fp32 scatter [b,h,s,dk]. MODE 1: fp32 row-major. MODE 2: bf16 hi/lo
// scatter [b,h,s,dk].
// ===========================================================================
constexpr int PITCH = 40;              // bf16 elems per smem row (80B)
constexpr int TKS = 32;
constexpr int NST = DIM / TKS;         // 32
constexpr int ARR_B = 128 * PITCH * 2; // 10240 B per array
constexpr int STG_B = 4 * ARR_B;       // 40960 B per stage
constexpr int SMEM_GEMM = 2 * STG_B;   // 81920 B

template <int MODE>
__device__ __forceinline__ void gemm2_body(
    const __nv_bfloat16* __restrict__ Ah, const __nv_bfloat16* __restrict__ Al,
    const __nv_bfloat16* __restrict__ Bh, const __nv_bfloat16* __restrict__ Bl,
    float* __restrict__ C, __nv_bfloat16* __restrict__ Ch,
    __nv_bfloat16* __restrict__ Cl)
{
    extern __shared__ char smraw[];
    const uint32_t sb = smem_u32(smraw);

    const int tid  = threadIdx.x;
    const int wid  = tid >> 5;
    const int lane = tid & 31;
    const int wm   = wid & 1;
    const int wn   = wid >> 1;
    const int m0   = blockIdx.y * 128;
    const int n0   = blockIdx.x * 128;

    // cp.async mapping: thread -> (array, 2 rows, 4 chunks/row)
    const int arr   = tid >> 6;            // 0..3  (Ah, Al, Bh, Bl)
    const int lrow2 = (tid & 63) * 2;
    const __nv_bfloat16* gsrc =
        (arr == 0) ? Ah : (arr == 1) ? Al : (arr == 2) ? Bh : Bl;
    const int r0 = (arr < 2) ? m0 : n0;
    const __nv_bfloat16* srow = gsrc + (size_t)(r0 + lrow2) * DIM;
    const uint32_t dbase0 = sb + arr * ARR_B + lrow2 * (PITCH * 2);

    auto issue = [&](int s) {
        const int k0 = s * TKS;
        const uint32_t db = dbase0 + (s & 1) * STG_B;
        #pragma unroll
        for (int i = 0; i < 8; i++) {
            const int rr = i >> 2, ch = i & 3;
            cp16(db + rr * (PITCH * 2) + ch * 16, srow + rr * DIM + k0 + ch * 8);
        }
        CP_COMMIT();
    };

    // ldmatrix lane addressing
    const int a_r = wm * 64 + (lane & 15);
    const int a_c = (lane >> 4) * 8;
    const int b_r = wn * 32 + (lane & 7);
    const int b_c = ((lane >> 3) & 1) * 8;

    float acc[4][4][4];
    #pragma unroll
    for (int i = 0; i < 4; i++)
        #pragma unroll
        for (int j = 0; j < 4; j++)
            #pragma unroll
            for (int q = 0; q < 4; q++) acc[i][j][q] = 0.0f;

    issue(0);
    issue(1);

    for (int s = 0; s < NST; s++) {
        if (s + 1 < NST) cp_wait<1>(); else cp_wait<0>();
        __syncthreads();

        const uint32_t stg = sb + (s & 1) * STG_B;
        const uint32_t aAh = stg, aAl = stg + ARR_B;
        const uint32_t aBh = stg + 2 * ARR_B, aBl = stg + 3 * ARR_B;

        #pragma unroll
        for (int ks = 0; ks < 2; ks++) {
            uint32_t Ahf[4][4], Alf[4][4], Bhf[4][2], Blf[4][2];
            const int ac = ks * 16 + a_c;
            const int bc = ks * 16 + b_c;
            #pragma unroll
            for (int mi = 0; mi < 4; mi++) {
                const uint32_t off = ((a_r + mi * 16) * PITCH + ac) * 2;
                ldm_x4(Ahf[mi], aAh + off);
                ldm_x4(Alf[mi], aAl + off);
            }
            #pragma unroll
            for (int ni = 0; ni < 4; ni++) {
                const uint32_t off = ((b_r + ni * 8) * PITCH + bc) * 2;
                ldm_x2(Bhf[ni], aBh + off);
                ldm_x2(Blf[ni], aBl + off);
            }
            #pragma unroll
            for (int mi = 0; mi < 4; mi++)
                #pragma unroll
                for (int ni = 0; ni < 4; ni++) {
                    mma16816(acc[mi][ni], Ahf[mi], Bhf[ni]);
                    mma16816(acc[mi][ni], Ahf[mi], Blf[ni]);
                    mma16816(acc[mi][ni], Alf[mi], Bhf[ni]);
                }
        }
        __syncthreads();
        if (s + 2 < NST) issue(s + 2);
    }

    // epilogue
    const int er = m0 + wm * 64 + (lane >> 2);
    const int ec = n0 + wn * 32 + (lane & 3) * 2;
    #pragma unroll
    for (int mi = 0; mi < 4; mi++) {
        #pragma unroll
        for (int ni = 0; ni < 4; ni++) {
            const int col = ec + ni * 8;
            #pragma unroll
            for (int half = 0; half < 2; half++) {
                const int row = er + mi * 16 + half * 8;
                const float vx = acc[mi][ni][half * 2];
                const float vy = acc[mi][ni][half * 2 + 1];
                if (MODE == 1) {
                    *(float2*)(C + (size_t)row * DIM + col) = make_float2(vx, vy);
                } else {
                    const int b = row >> 11, sq = row & (SEQ - 1);
                    const int h = col >> 6, dk = col & (HDIM - 1);
                    const size_t idx = ((size_t)(b * NHEAD + h) * SEQ + sq) * HDIM + dk;
                    if (MODE == 0) {
                        *(float2*)(C + idx) = make_float2(vx, vy);
                    } else {
                        uint32_t hi, lo;
                        pack_hl(vx, vy, hi, lo);
                        *(uint32_t*)(Ch + idx) = hi;
                        *(uint32_t*)(Cl + idx) = lo;
                    }
                }
            }
        }
    }
}

__global__ void __launch_bounds__(256, 1)
gemm_qkv2()
{
    const int sel = blockIdx.z;
    if (sel == 0)
        gemm2_body<0>(aqh, aql, wqh, wql, g_q, nullptr, nullptr);
    else if (sel == 1)
        gemm2_body<0>(akh, akl, wkh, wkl, g_k, nullptr, nullptr);
    else
        gemm2_body<2>(avh, avl, wvh, wvl, nullptr, vh_g, vl_g);
}

__global__ void __launch_bounds__(256, 1)
gemm_o2(float* __restrict__ out)
{
    gemm2_body<1>(xh_g, xl_g, woh, wol, out, nullptr, nullptr);
}

// ---------------------------------------------------------------------------
// RoPE v2: reads fp32 g_q/g_k, writes hi/lo bf16 (qh/ql, kh/kl)
// ---------------------------------------------------------------------------
__global__ void __launch_bounds__(256)
rope2_kernel()
{
    const int isK = blockIdx.y;
    const float* X = isK ? g_k : g_q;
    __nv_bfloat16* Dh = isK ? kh_g : qh_g;
    __nv_bfloat16* Dl = isK ? kl_g : ql_g;

    const size_t idx = (size_t)blockIdx.x * blockDim.x + threadIdx.x;
    const int j = (int)(idx & 31);
    const size_t row = idx >> 5;
    const int s = (int)(row & (SEQ - 1));

    const float e = (float)(2 * j) * (1.0f / 64.0f);
    const float inv_freq = 1.0f / powf(10000.0f, e);
    float sn, cs;
    sincosf((float)s * inv_freq, &sn, &cs);

    float2 x = *(const float2*)(X + row * HDIM + 2 * j);
    const float yx = x.x * cs - x.y * sn;
    const float yy = x.y * cs + x.x * sn;
    uint32_t hi, lo;
    pack_hl(yx, yy, hi, lo);
    *(uint32_t*)(Dh + row * HDIM + 2 * j) = hi;
    *(uint32_t*)(Dl + row * HDIM + 2 * j) = lo;
}

// ===========================================================================
// Attention v2: pre-split bf16 Q/K/V, cp.async double-buffered K/V tiles.
// CTA = one (b,h) x 128 q rows, 4 warps. 64-key tiles, split-3 mma.
// ===========================================================================
constexpr int QB  = 128;
constexpr int KTL = 64;
constexpr int PQ  = 72;                       // smem pitch (bf16 elems), 144B
constexpr int QARR_B  = QB * PQ * 2;          // 18432
constexpr int KVARR_B = KTL * PQ * 2;         // 9216
constexpr int KVBUF_B = 4 * KVARR_B;          // 36864
constexpr int OFF_QH2 = 0;
constexpr int OFF_QL2 = QARR_B;
constexpr int OFF_KV  = 2 * QARR_B;           // 36864
constexpr int OFF_MB2 = OFF_KV + 2 * KVBUF_B; // 110592
constexpr int SMEM_ATTN = OFF_MB2 + 2 * KTL * 4; // 111104
constexpr int NT = SEQ / KTL;                 // 32

constexpr float SCALE2 = 0.18033688011f;      // 0.125 * log2(e)
constexpr float MBIAS2 = -14426.950409f;      // -10000 * log2(e)

__global__ void __launch_bounds__(128, 2)
attn_mma2(const int* __restrict__ mask)
{
    extern __shared__ char sm[];
    const uint32_t sb = smem_u32(sm);
    int* sMbI = (int*)(sm + OFF_MB2);

    const int tid = threadIdx.x;
    const int wid = tid >> 5, lane = tid & 31;
    const int bh = blockIdx.y, b = bh >> 4, h = bh & 15;
    const int q0 = blockIdx.x * QB;

    const __nv_bfloat16* Qh = qh_g + ((size_t)bh * SEQ + q0) * HDIM;
    const __nv_bfloat16* Ql = ql_g + ((size_t)bh * SEQ + q0) * HDIM;
    const size_t kvbase = (size_t)bh * SEQ * HDIM;

    // issue Q (once)
    {
        const uint32_t dq = sb + OFF_QH2 + tid * (PQ * 2);
        const uint32_t dql = sb + OFF_QL2 + tid * (PQ * 2);
        const __nv_bfloat16* sq = Qh + (size_t)tid * HDIM;
        const __nv_bfloat16* sql = Ql + (size_t)tid * HDIM;
        #pragma unroll
        for (int i = 0; i < 8; i++) {
            cp16(dq + i * 16, sq + i * 8);
            cp16(dql + i * 16, sql + i * 8);
        }
    }

    // K/V tile issue: thread -> (array, 2 rows, 8 chunks/row)
    const int kvarr = tid >> 5;               // 0..3 (Kh,Kl,Vh,Vl)
    const int kvrow2 = (tid & 31) * 2;
    const __nv_bfloat16* kvsrc =
        (kvarr == 0) ? kh_g : (kvarr == 1) ? kl_g : (kvarr == 2) ? vh_g : vl_g;
    const __nv_bfloat16* kvrow = kvsrc + kvbase + (size_t)kvrow2 * HDIM;
    const uint32_t kvd0 = sb + OFF_KV + kvarr * KVARR_B + kvrow2 * (PQ * 2);

    auto issue_kv = [&](int t) {
        const int buf = t & 1;
        const uint32_t db = kvd0 + buf * KVBUF_B;
        const __nv_bfloat16* srcr = kvrow + (size_t)t * KTL * HDIM;
        #pragma unroll
        for (int i = 0; i < 16; i++) {
            const int rr = i >> 3, ch = i & 7;
            cp16(db + rr * (PQ * 2) + ch * 16, srcr + rr * HDIM + ch * 8);
        }
        if (tid < 16)
            cp16(sb + OFF_MB2 + buf * (KTL * 4) + tid * 16,
                 mask + b * SEQ + t * KTL + tid * 4);
        CP_COMMIT();
    };

    issue_kv(0);   // group 0 (includes Q)
    issue_kv(1);   // group 1

    float accO[2][8][4];
    #pragma unroll
    for (int mi = 0; mi < 2; mi++)
        #pragma unroll
        for (int ni = 0; ni < 8; ni++)
            #pragma unroll
            for (int v = 0; v < 4; v++) accO[mi][ni][v] = 0.0f;
    float mrow[2][2] = {{-1e30f, -1e30f}, {-1e30f, -1e30f}};
    float lrow[2][2] = {{0.0f, 0.0f}, {0.0f, 0.0f}};

    const int wq0 = wid * 32;
    const uint32_t aQh = sb + OFF_QH2, aQl = sb + OFF_QL2;

    const int qa = (lane & 15) * PQ + (lane >> 4) * 8;
    const int ka = ((lane & 7) + ((lane >> 4) & 1) * 8) * PQ + ((lane >> 3) & 1) * 8;
    const int va = ((lane & 7) + ((lane >> 3) & 1) * 8) * PQ + ((lane >> 4) & 1) * 8;

    for (int t = 0; t < NT; t++) {
        if (t + 1 < NT) cp_wait<1>(); else cp_wait<0>();
        __syncthreads();

        const int buf = t & 1;
        const uint32_t kvb = sb + OFF_KV + buf * KVBUF_B;
        const uint32_t aKh = kvb, aKl = kvb + KVARR_B;
        const uint32_t aVh = kvb + 2 * KVARR_B, aVl = kvb + 3 * KVARR_B;

        // mask biases for this thread's 16 columns
        float bias0[8], bias1[8];
        const int* mb = sMbI + buf * KTL;
        #pragma unroll
        for (int ni = 0; ni < 8; ni++) {
            bias0[ni] = mb[ni * 8 + (lane & 3) * 2]     ? 0.0f : MBIAS2;
            bias1[ni] = mb[ni * 8 + (lane & 3) * 2 + 1] ? 0.0f : MBIAS2;
        }

        // ---- S = Q K^T (split-3) ----
        float acc[2][8][4];
        #pragma unroll
        for (int mi = 0; mi < 2; mi++)
            #pragma unroll
            for (int ni = 0; ni < 8; ni++)
                #pragma unroll
                for (int v = 0; v < 4; v++) acc[mi][ni][v] = 0.0f;

        #pragma unroll
        for (int ks = 0; ks < 4; ks++) {
            uint32_t qhf[2][4], qlf[2][4];
            #pragma unroll
            for (int mi = 0; mi < 2; mi++) {
                const uint32_t off = 2 * ((wq0 + mi * 16) * PQ + ks * 16 + qa);
                ldm_x4(qhf[mi], aQh + off);
                ldm_x4(qlf[mi], aQl + off);
            }
            #pragma unroll
            for (int nip = 0; nip < 4; nip++) {
                uint32_t khf[4], klf[4];
                const uint32_t off = 2 * (nip * 16 * PQ + ks * 16 + ka);
                ldm_x4(khf, aKh + off);
                ldm_x4(klf, aKl + off);
                #pragma unroll
                for (int mi = 0; mi < 2; mi++)
                    #pragma unroll
                    for (int j = 0; j < 2; j++) {
                        const int ni = nip * 2 + j;
                        mma16816(acc[mi][ni], qhf[mi], &khf[2 * j]);
                        mma16816(acc[mi][ni], qhf[mi], &klf[2 * j]);
                        mma16816(acc[mi][ni], qlf[mi], &khf[2 * j]);
                    }
            }
        }

        // ---- online softmax ----
        #pragma unroll
        for (int mi = 0; mi < 2; mi++) {
            #pragma unroll
            for (int half = 0; half < 2; half++) {
                float mt = -1e30f;
                #pragma unroll
                for (int ni = 0; ni < 8; ni++) {
                    float v0 = fmaf(acc[mi][ni][half * 2],     SCALE2, bias0[ni]);
                    float v1 = fmaf(acc[mi][ni][half * 2 + 1], SCALE2, bias1[ni]);
                    acc[mi][ni][half * 2]     = v0;
                    acc[mi][ni][half * 2 + 1] = v1;
                    mt = fmaxf(mt, fmaxf(v0, v1));
                }
                mt = fmaxf(mt, __shfl_xor_sync(0xFFFFFFFFu, mt, 1));
                mt = fmaxf(mt, __shfl_xor_sync(0xFFFFFFFFu, mt, 2));
                const float mold = mrow[mi][half];
                const float mnew = fmaxf(mold, mt);
                const float corr = exp2fast(mold - mnew);
                mrow[mi][half] = mnew;
                lrow[mi][half] *= corr;
                float lsum = 0.0f;
                #pragma unroll
                for (int ni = 0; ni < 8; ni++) {
                    float p0 = exp2fast(acc[mi][ni][half * 2]     - mnew);
                    float p1 = exp2fast(acc[mi][ni][half * 2 + 1] - mnew);
                    acc[mi][ni][half * 2]     = p0;
                    acc[mi][ni][half * 2 + 1] = p1;
                    lsum += p0 + p1;
                    accO[mi][ni][half * 2]     *= corr;
                    accO[mi][ni][half * 2 + 1] *= corr;
                }
                lrow[mi][half] += lsum;
            }
        }

        // ---- O += P V (split-3) ----
        #pragma unroll
        for (int kf = 0; kf < 4; kf++) {
            uint32_t pah[2][4], pal[2][4];
            #pragma unroll
            for (int mi = 0; mi < 2; mi++) {
                pack_hl(acc[mi][2 * kf][0],     acc[mi][2 * kf][1],     pah[mi][0], pal[mi][0]);
                pack_hl(acc[mi][2 * kf][2],     acc[mi][2 * kf][3],     pah[mi][1], pal[mi][1]);
                pack_hl(acc[mi][2 * kf + 1][0], acc[mi][2 * kf + 1][1], pah[mi][2], pal[mi][2]);
                pack_hl(acc[mi][2 * kf + 1][2], acc[mi][2 * kf + 1][3], pah[mi][3], pal[mi][3]);
            }
            #pragma unroll
            for (int nip = 0; nip < 4; nip++) {
                uint32_t vhf[4], vlf[4];
                const uint32_t off = 2 * (kf * 16 * PQ + nip * 16 + va);
                ldm_x4_t(vhf, aVh + off);
                ldm_x4_t(vlf, aVl + off);
                #pragma unroll
                for (int mi = 0; mi < 2; mi++)
                    #pragma unroll
                    for (int j = 0; j < 2; j++) {
                        const int ni = nip * 2 + j;
                        mma16816(accO[mi][ni], pah[mi], &vhf[2 * j]);
                        mma16816(accO[mi][ni], pah[mi], &vlf[2 * j]);
                        mma16816(accO[mi][ni], pal[mi], &vhf[2 * j]);
                    }
            }
        }

        __syncthreads();
        if (t + 2 < NT) issue_kv(t + 2);
    }

    // ---- epilogue: reduce l, normalize, pack hi/lo to xh/xl ----
    float inv[2][2];
    #pragma unroll
    for (int mi = 0; mi < 2; mi++)
        #pragma unroll
        for (int half = 0; half < 2; half++) {
            float l = lrow[mi][half];
            l += __shfl_xor_sync(0xFFFFFFFFu, l, 1);
            l += __shfl_xor_sync(0xFFFFFFFFu, l, 2);
            inv[mi][half] = 1.0f / l;
        }

    #pragma unroll
    for (int mi = 0; mi < 2; mi++)
        #pragma unroll
        for (int ni = 0; ni < 8; ni++)
            #pragma unroll
            for (int half = 0; half < 2; half++) {
                const int row = q0 + wq0 + mi * 16 + (lane >> 2) + half * 8;
                const int col = ni * 8 + (lane & 3) * 2;
                const float vx = accO[mi][ni][half * 2] * inv[mi][half];
                const float vy = accO[mi][ni][half * 2 + 1] * inv[mi][half];
                uint32_t hi, lo;
                pack_hl(vx, vy, hi, lo);
                const size_t idx = ((size_t)(b * SEQ + row)) * DIM + h * HDIM + col;
                *(uint32_t*)(xh_g + idx) = hi;
                *(uint32_t*)(xl_g + idx) = lo;
            }
}

// ---------------------------------------------------------------------------
// Launch
// ---------------------------------------------------------------------------
extern "C" void kernel_launch(void* const* d_in, const int* in_sizes, int n_in,
                              void* d_out, int out_size)
{
    const float* q    = (const float*)d_in[0];
    const float* k    = (const float*)d_in[1];
    const float* v    = (const float*)d_in[2];
    const int*   mask = (const int*)  d_in[3];
    const float* w_q  = (const float*)d_in[4];
    const float* w_k  = (const float*)d_in[5];
    const float* w_v  = (const float*)d_in[6];
    const float* w_o  = (const float*)d_in[7];
    float* out = (float*)d_out;

    cudaFuncSetAttribute(gemm_qkv2, cudaFuncAttributeMaxDynamicSharedMemorySize, SMEM_GEMM);
    cudaFuncSetAttribute(gemm_o2,   cudaFuncAttributeMaxDynamicSharedMemorySize, SMEM_GEMM);
    cudaFuncSetAttribute(attn_mma2, cudaFuncAttributeMaxDynamicSharedMemorySize, SMEM_ATTN);

    // 0) pre-split inputs and weights into hi/lo bf16
    conv_inputs<<<dim3(NTOK * DIM / 1024, 1, 3), 256>>>(q, k, v);
    conv_weights<<<dim3(DIM * DIM / 1024, 1, 4), 256>>>(w_q, w_k, w_v, w_o);

    // 1) Q/K/V projections (cp.async pipelined tensor-core GEMM)
    gemm_qkv2<<<dim3(DIM / 128, NTOK / 128, 3), 256, SMEM_GEMM>>>();

    // 2) RoPE -> hi/lo bf16 Q/K
    rope2_kernel<<<dim3((BHS * SEQ * 32) / 256, 2), 256>>>();

    // 3) Flash attention (tensor cores, double-buffered K/V)
    attn_mma2<<<dim3(SEQ / QB, BHS), 128, SMEM_ATTN>>>(mask);

    // 4) Output projection
    gemm_o2<<<dim3(DIM / 128, NTOK / 128), 256, SMEM_GEMM>>>(out);
}

// round 7
// speedup vs baseline: 1.1301x; 1.1301x over previous
#include <cuda_runtime.h>
#include <cuda_bf16.h>
#include <math.h>
#include <stdint.h>

// Problem constants
constexpr int BATCH = 4;
constexpr int SEQ   = 2048;
constexpr int DIM   = 1024;
constexpr int NHEAD = 16;
constexpr int HDIM  = 64;
constexpr int NTOK  = BATCH * SEQ;   // 8192
constexpr int BHS   = BATCH * NHEAD; // 64

// Scratch
__device__ float g_q[BHS * SEQ * HDIM]; // [b,h,s,dk]
__device__ float g_k[BHS * SEQ * HDIM];
__device__ float g_v[BHS * SEQ * HDIM];
__device__ float g_x[NTOK * DIM];       // attn out, [b,s,h*dk]

// ---------------------------------------------------------------------------
// Helpers
// ---------------------------------------------------------------------------
__device__ __forceinline__ uint32_t smem_u32(const void* p) {
    uint32_t a;
    asm("{ .reg .u64 t; cvta.to.shared.u64 t, %1; cvt.u32.u64 %0, t; }"
        : "=r"(a) : "l"(p));
    return a;
}
__device__ __forceinline__ void ldm_x4(uint32_t* r, uint32_t addr) {
    asm volatile("ldmatrix.sync.aligned.m8n8.x4.shared.b16 {%0,%1,%2,%3}, [%4];"
        : "=r"(r[0]), "=r"(r[1]), "=r"(r[2]), "=r"(r[3]) : "r"(addr));
}
__device__ __forceinline__ void ldm_x4_t(uint32_t* r, uint32_t addr) {
    asm volatile("ldmatrix.sync.aligned.m8n8.x4.trans.shared.b16 {%0,%1,%2,%3}, [%4];"
        : "=r"(r[0]), "=r"(r[1]), "=r"(r[2]), "=r"(r[3]) : "r"(addr));
}
__device__ __forceinline__ void ldm_x2(uint32_t* r, uint32_t addr) {
    asm volatile("ldmatrix.sync.aligned.m8n8.x2.shared.b16 {%0,%1}, [%2];"
        : "=r"(r[0]), "=r"(r[1]) : "r"(addr));
}
__device__ __forceinline__ void mma16816(float* c, const uint32_t* a, const uint32_t* b) {
    asm volatile(
        "mma.sync.aligned.m16n8k16.row.col.f32.bf16.bf16.f32 "
        "{%0,%1,%2,%3}, {%4,%5,%6,%7}, {%8,%9}, {%0,%1,%2,%3};"
        : "+f"(c[0]), "+f"(c[1]), "+f"(c[2]), "+f"(c[3])
        : "r"(a[0]), "r"(a[1]), "r"(a[2]), "r"(a[3]), "r"(b[0]), "r"(b[1]));
}
__device__ __forceinline__ void cvt_hl(float4 v, uint2& hi, uint2& lo) {
    __nv_bfloat162 h0 = __floats2bfloat162_rn(v.x, v.y);
    __nv_bfloat162 h1 = __floats2bfloat162_rn(v.z, v.w);
    float2 f0 = __bfloat1622float2(h0);
    float2 f1 = __bfloat1622float2(h1);
    __nv_bfloat162 l0 = __floats2bfloat162_rn(v.x - f0.x, v.y - f0.y);
    __nv_bfloat162 l1 = __floats2bfloat162_rn(v.z - f1.x, v.w - f1.y);
    hi.x = *(uint32_t*)&h0; hi.y = *(uint32_t*)&h1;
    lo.x = *(uint32_t*)&l0; lo.y = *(uint32_t*)&l1;
}
__device__ __forceinline__ void pack_hl(float a, float b, uint32_t& hi, uint32_t& lo) {
    __nv_bfloat162 h = __floats2bfloat162_rn(a, b);
    float2 hf = __bfloat1622float2(h);
    __nv_bfloat162 l = __floats2bfloat162_rn(a - hf.x, b - hf.y);
    hi = *(uint32_t*)&h;
    lo = *(uint32_t*)&l;
}
// FFMA-only exp2
__device__ __forceinline__ float exp2fast(float y) {
    y = fmaxf(y, -80.0f);
    float t = y + 12582912.0f;
    float f = y - (t - 12582912.0f);
    float p = 0.0013333558f;
    p = fmaf(p, f, 0.0096181291f);
    p = fmaf(p, f, 0.0555041087f);
    p = fmaf(p, f, 0.2402265069f);
    p = fmaf(p, f, 0.6931471806f);
    p = fmaf(p, f, 1.0f);
    return __int_as_float(__float_as_int(p) + (__float_as_int(t) << 23));
}

// ===========================================================================
// GEMM v3: C = A @ W^T, split-3 bf16 HMMA.
// CTA tile 128(M) x 64(N), 8 warps as 4M x 2N, warp tile 32x32.
// K staged 32 wide, register prefetch, 2 CTAs/SM.
// ===========================================================================
constexpr int TKS = 32;
constexpr int NST = DIM / TKS;
constexpr int PITCH = 40;

template <int MODE>
__device__ __forceinline__ void gemm3_body(const float* __restrict__ A,
                                           const float* __restrict__ W,
                                           float* __restrict__ C)
{
    __shared__ __align__(16) __nv_bfloat16 sAh[128 * PITCH];
    __shared__ __align__(16) __nv_bfloat16 sAl[128 * PITCH];
    __shared__ __align__(16) __nv_bfloat16 sBh[64 * PITCH];
    __shared__ __align__(16) __nv_bfloat16 sBl[64 * PITCH];

    const int tid  = threadIdx.x;
    const int wid  = tid >> 5;
    const int lane = tid & 31;
    const int wm   = wid >> 1;       // 0..3 (32 rows each)
    const int wn   = wid & 1;        // 0..1 (32 cols each)
    const int m0   = blockIdx.y * 128;
    const int n0   = blockIdx.x * 64;

    const int larow = tid >> 1;
    const int lacol = (tid & 1) * 16;
    const float4* arow = (const float4*)(A + (size_t)(m0 + larow) * DIM + lacol);
    const int soffA = larow * PITCH + lacol;
    const int lbrow = tid >> 2;
    const int lbcol = (tid & 3) * 8;
    const float4* brow = (const float4*)(W + (size_t)(n0 + lbrow) * DIM + lbcol);
    const int soffB = lbrow * PITCH + lbcol;

    const uint32_t aAh = smem_u32(sAh), aAl = smem_u32(sAl);
    const uint32_t aBh = smem_u32(sBh), aBl = smem_u32(sBl);
    const int a_r = wm * 32 + (lane & 15);
    const int a_c = (lane >> 4) * 8;
    const int b_r = wn * 32 + (lane & 7);
    const int b_c = ((lane >> 3) & 1) * 8;

    float acc[2][4][4];
    #pragma unroll
    for (int i = 0; i < 2; i++)
        #pragma unroll
        for (int j = 0; j < 4; j++)
            #pragma unroll
            for (int q = 0; q < 4; q++) acc[i][j][q] = 0.0f;

    float4 ra[4], rb[2];
    #pragma unroll
    for (int i = 0; i < 4; i++) ra[i] = arow[i];
    #pragma unroll
    for (int i = 0; i < 2; i++) rb[i] = brow[i];
    {
        uint2 hi, lo;
        #pragma unroll
        for (int i = 0; i < 4; i++) {
            cvt_hl(ra[i], hi, lo);
            *(uint2*)(sAh + soffA + i * 4) = hi;
            *(uint2*)(sAl + soffA + i * 4) = lo;
        }
        #pragma unroll
        for (int i = 0; i < 2; i++) {
            cvt_hl(rb[i], hi, lo);
            *(uint2*)(sBh + soffB + i * 4) = hi;
            *(uint2*)(sBl + soffB + i * 4) = lo;
        }
    }
    __syncthreads();

    for (int s = 0; s < NST; s++) {
        if (s + 1 < NST) {
            const int koff = ((s + 1) * TKS) >> 2;
            #pragma unroll
            for (int i = 0; i < 4; i++) ra[i] = arow[koff + i];
            #pragma unroll
            for (int i = 0; i < 2; i++) rb[i] = brow[koff + i];
        }

        #pragma unroll
        for (int ks = 0; ks < 2; ks++) {
            uint32_t Ahf[2][4], Alf[2][4];
            const int ac = ks * 16 + a_c;
            const int bc = ks * 16 + b_c;
            #pragma unroll
            for (int mi = 0; mi < 2; mi++) {
                const uint32_t off = ((a_r + mi * 16) * PITCH + ac) * 2;
                ldm_x4(Ahf[mi], aAh + off);
                ldm_x4(Alf[mi], aAl + off);
            }
            #pragma unroll
            for (int ni = 0; ni < 4; ni++) {
                uint32_t Bhf[2], Blf[2];
                const uint32_t off = ((b_r + ni * 8) * PITCH + bc) * 2;
                ldm_x2(Bhf, aBh + off);
                ldm_x2(Blf, aBl + off);
                #pragma unroll
                for (int mi = 0; mi < 2; mi++) {
                    mma16816(acc[mi][ni], Ahf[mi], Bhf);
                    mma16816(acc[mi][ni], Ahf[mi], Blf);
                    mma16816(acc[mi][ni], Alf[mi], Bhf);
                }
            }
        }
        __syncthreads();
        if (s + 1 < NST) {
            uint2 hi, lo;
            #pragma unroll
            for (int i = 0; i < 4; i++) {
                cvt_hl(ra[i], hi, lo);
                *(uint2*)(sAh + soffA + i * 4) = hi;
                *(uint2*)(sAl + soffA + i * 4) = lo;
            }
            #pragma unroll
            for (int i = 0; i < 2; i++) {
                cvt_hl(rb[i], hi, lo);
                *(uint2*)(sBh + soffB + i * 4) = hi;
                *(uint2*)(sBl + soffB + i * 4) = lo;
            }
            __syncthreads();
        }
    }

    const int er = m0 + wm * 32 + (lane >> 2);
    const int ec = n0 + wn * 32 + (lane & 3) * 2;
    #pragma unroll
    for (int mi = 0; mi < 2; mi++) {
        #pragma unroll
        for (int ni = 0; ni < 4; ni++) {
            const int col = ec + ni * 8;
            #pragma unroll
            for (int half = 0; half < 2; half++) {
                const int row = er + mi * 16 + half * 8;
                float2 v = make_float2(acc[mi][ni][half * 2],
                                       acc[mi][ni][half * 2 + 1]);
                if (MODE == 0) {
                    const int b = row >> 11, sq = row & (SEQ - 1);
                    const int h = col >> 6, dk = col & (HDIM - 1);
                    *(float2*)(C + ((size_t)(b * NHEAD + h) * SEQ + sq) * HDIM + dk) = v;
                } else {
                    *(float2*)(C + (size_t)row * DIM + col) = v;
                }
            }
        }
    }
}

__global__ void __launch_bounds__(256, 2)
gemm_qkv_tc(const float* __restrict__ Aq, const float* __restrict__ Ak,
            const float* __restrict__ Av, const float* __restrict__ Wq,
            const float* __restrict__ Wk, const float* __restrict__ Wv)
{
    const int sel = blockIdx.z;
    const float* A = (sel == 0) ? Aq : (sel == 1) ? Ak : Av;
    const float* W = (sel == 0) ? Wq : (sel == 1) ? Wk : Wv;
    float* C = (sel == 0) ? g_q : (sel == 1) ? g_k : g_v;
    gemm3_body<0>(A, W, C);
}

__global__ void __launch_bounds__(256, 2)
gemm_out_tc(const float* __restrict__ Wo, float* __restrict__ C)
{
    gemm3_body<1>(g_x, Wo, C);
}

// ---------------------------------------------------------------------------
// RoPE (interleaved pairs), in-place on g_q / g_k
// ---------------------------------------------------------------------------
__global__ void __launch_bounds__(256)
rope_kernel()
{
    float* X = blockIdx.y ? g_k : g_q;
    const size_t idx = (size_t)blockIdx.x * blockDim.x + threadIdx.x;
    const int j = (int)(idx & 31);
    const size_t row = idx >> 5;
    const int s = (int)(row & (SEQ - 1));

    const float e = (float)(2 * j) * (1.0f / 64.0f);
    const float inv_freq = 1.0f / powf(10000.0f, e);
    float sn, cs;
    sincosf((float)s * inv_freq, &sn, &cs);

    float2 x = *(float2*)(X + row * HDIM + 2 * j);
    float2 y;
    y.x = x.x * cs - x.y * sn;
    y.y = x.y * cs + x.x * sn;
    *(float2*)(X + row * HDIM + 2 * j) = y;
}

// ===========================================================================
// Tensor-core flash attention (full split-3 in both QK^T and PV — R4 proven).
// CTA = one (b,h) x 128 q rows. 4 warps x 32 rows. 64-key tiles.
// ===========================================================================
constexpr int QB  = 128;
constexpr int KTL = 64;
constexpr int PQ  = 72;

constexpr int OFF_QH = 0;
constexpr int OFF_QL = OFF_QH + QB * PQ * 2;
constexpr int OFF_KH = OFF_QL + QB * PQ * 2;
constexpr int OFF_KL = OFF_KH + KTL * PQ * 2;
constexpr int OFF_VH = OFF_KL + KTL * PQ * 2;
constexpr int OFF_VL = OFF_VH + KTL * PQ * 2;
constexpr int OFF_MB = OFF_VL + KTL * PQ * 2;
constexpr int SMEM_ATTN = OFF_MB + KTL * 4;

constexpr float SCALE2 = 0.18033688011f;      // 0.125 * log2(e)
constexpr float MBIAS2 = -14426.950409f;      // -10000 * log2(e)

__global__ void __launch_bounds__(128, 1)
attn_mma_kernel(const int* __restrict__ mask)
{
    extern __shared__ char sm[];
    __nv_bfloat16* sQh = (__nv_bfloat16*)(sm + OFF_QH);
    __nv_bfloat16* sQl = (__nv_bfloat16*)(sm + OFF_QL);
    __nv_bfloat16* sKh = (__nv_bfloat16*)(sm + OFF_KH);
    __nv_bfloat16* sKl = (__nv_bfloat16*)(sm + OFF_KL);
    __nv_bfloat16* sVh = (__nv_bfloat16*)(sm + OFF_VH);
    __nv_bfloat16* sVl = (__nv_bfloat16*)(sm + OFF_VL);
    float* sMb = (float*)(sm + OFF_MB);

    const int tid = threadIdx.x;
    const int wid = tid >> 5, lane = tid & 31;
    const int bh = blockIdx.y, b = bh >> 4, h = bh & 15;
    const int q0 = blockIdx.x * QB;

    const float* Qg = g_q + ((size_t)bh * SEQ + q0) * HDIM;
    const float* Kg = g_k + (size_t)bh * SEQ * HDIM;
    const float* Vg = g_v + (size_t)bh * SEQ * HDIM;

    {
        const float4* src = (const float4*)(Qg + (size_t)tid * HDIM);
        __nv_bfloat16* dh = sQh + tid * PQ;
        __nv_bfloat16* dl = sQl + tid * PQ;
        #pragma unroll
        for (int i = 0; i < 16; i++) {
            uint2 hi, lo;
            cvt_hl(src[i], hi, lo);
            *(uint2*)(dh + i * 4) = hi;
            *(uint2*)(dl + i * 4) = lo;
        }
    }

    float accO[2][8][4];
    #pragma unroll
    for (int mi = 0; mi < 2; mi++)
        #pragma unroll
        for (int ni = 0; ni < 8; ni++)
            #pragma unroll
            for (int v = 0; v < 4; v++) accO[mi][ni][v] = 0.0f;
    float mrow[2][2] = {{-1e30f, -1e30f}, {-1e30f, -1e30f}};
    float lrow[2][2] = {{0.0f, 0.0f}, {0.0f, 0.0f}};

    const int wq0 = wid * 32;
    const uint32_t aQh = smem_u32(sQh), aQl = smem_u32(sQl);
    const uint32_t aKh = smem_u32(sKh), aKl = smem_u32(sKl);
    const uint32_t aVh = smem_u32(sVh), aVl = smem_u32(sVl);

    const int qa = (lane & 15) * PQ + (lane >> 4) * 8;
    const int ka = ((lane & 7) + ((lane >> 4) & 1) * 8) * PQ + ((lane >> 3) & 1) * 8;
    const int va = ((lane & 7) + ((lane >> 3) & 1) * 8) * PQ + ((lane >> 4) & 1) * 8;

    const int ldk  = tid >> 1;
    const int ldc0 = (tid & 1) * 32;

    for (int kt = 0; kt < SEQ; kt += KTL) {
        __syncthreads();
        {
            const float4* ksrc = (const float4*)(Kg + (size_t)(kt + ldk) * HDIM + ldc0);
            const float4* vsrc = (const float4*)(Vg + (size_t)(kt + ldk) * HDIM + ldc0);
            __nv_bfloat16* kh = sKh + ldk * PQ + ldc0;
            __nv_bfloat16* kl = sKl + ldk * PQ + ldc0;
            __nv_bfloat16* vh = sVh + ldk * PQ + ldc0;
            __nv_bfloat16* vl = sVl + ldk * PQ + ldc0;
            #pragma unroll
            for (int i = 0; i < 8; i++) {
                uint2 hi, lo;
                cvt_hl(ksrc[i], hi, lo);
                *(uint2*)(kh + i * 4) = hi;
                *(uint2*)(kl + i * 4) = lo;
                cvt_hl(vsrc[i], hi, lo);
                *(uint2*)(vh + i * 4) = hi;
                *(uint2*)(vl + i * 4) = lo;
            }
            if (tid < KTL)
                sMb[tid] = mask[b * SEQ + kt + tid] ? 0.0f : MBIAS2;
        }
        __syncthreads();

        float bias0[8], bias1[8];
        #pragma unroll
        for (int ni = 0; ni < 8; ni++) {
            bias0[ni] = sMb[ni * 8 + (lane & 3) * 2];
            bias1[ni] = sMb[ni * 8 + (lane & 3) * 2 + 1];
        }

        // ---- S = Q K^T (split-3) ----
        float acc[2][8][4];
        #pragma unroll
        for (int mi = 0; mi < 2; mi++)
            #pragma unroll
            for (int ni = 0; ni < 8; ni++)
                #pragma unroll
                for (int v = 0; v < 4; v++) acc[mi][ni][v] = 0.0f;

        #pragma unroll
        for (int ks = 0; ks < 4; ks++) {
            uint32_t qh[2][4], ql[2][4];
            #pragma unroll
            for (int mi = 0; mi < 2; mi++) {
                const uint32_t off = 2 * ((wq0 + mi * 16) * PQ + ks * 16 + qa);
                ldm_x4(qh[mi], aQh + off);
                ldm_x4(ql[mi], aQl + off);
            }
            #pragma unroll
            for (int nip = 0; nip < 4; nip++) {
                uint32_t kh[4], kl[4];
                const uint32_t off = 2 * (nip * 16 * PQ + ks * 16 + ka);
                ldm_x4(kh, aKh + off);
                ldm_x4(kl, aKl + off);
                #pragma unroll
                for (int mi = 0; mi < 2; mi++)
                    #pragma unroll
                    for (int j = 0; j < 2; j++) {
                        const int ni = nip * 2 + j;
                        mma16816(acc[mi][ni], qh[mi], &kh[2 * j]);
                        mma16816(acc[mi][ni], qh[mi], &kl[2 * j]);
                        mma16816(acc[mi][ni], ql[mi], &kh[2 * j]);
                    }
            }
        }

        // ---- online softmax ----
        #pragma unroll
        for (int mi = 0; mi < 2; mi++) {
            #pragma unroll
            for (int half = 0; half < 2; half++) {
                float mt = -1e30f;
                #pragma unroll
                for (int ni = 0; ni < 8; ni++) {
                    float v0 = fmaf(acc[mi][ni][half * 2],     SCALE2, bias0[ni]);
                    float v1 = fmaf(acc[mi][ni][half * 2 + 1], SCALE2, bias1[ni]);
                    acc[mi][ni][half * 2]     = v0;
                    acc[mi][ni][half * 2 + 1] = v1;
                    mt = fmaxf(mt, fmaxf(v0, v1));
                }
                mt = fmaxf(mt, __shfl_xor_sync(0xFFFFFFFFu, mt, 1));
                mt = fmaxf(mt, __shfl_xor_sync(0xFFFFFFFFu, mt, 2));
                const float mold = mrow[mi][half];
                const float mnew = fmaxf(mold, mt);
                const float corr = exp2fast(mold - mnew);
                mrow[mi][half] = mnew;
                lrow[mi][half] *= corr;
                float lsum = 0.0f;
                #pragma unroll
                for (int ni = 0; ni < 8; ni++) {
                    float p0 = exp2fast(acc[mi][ni][half * 2]     - mnew);
                    float p1 = exp2fast(acc[mi][ni][half * 2 + 1] - mnew);
                    acc[mi][ni][half * 2]     = p0;
                    acc[mi][ni][half * 2 + 1] = p1;
                    lsum += p0 + p1;
                    accO[mi][ni][half * 2]     *= corr;
                    accO[mi][ni][half * 2 + 1] *= corr;
                }
                lrow[mi][half] += lsum;
            }
        }

        // ---- O += P V (full split-3) ----
        #pragma unroll
        for (int kf = 0; kf < 4; kf++) {
            uint32_t pah[2][4], pal[2][4];
            #pragma unroll
            for (int mi = 0; mi < 2; mi++) {
                pack_hl(acc[mi][2 * kf][0],     acc[mi][2 * kf][1],     pah[mi][0], pal[mi][0]);
                pack_hl(acc[mi][2 * kf][2],     acc[mi][2 * kf][3],     pah[mi][1], pal[mi][1]);
                pack_hl(acc[mi][2 * kf + 1][0], acc[mi][2 * kf + 1][1], pah[mi][2], pal[mi][2]);
                pack_hl(acc[mi][2 * kf + 1][2], acc[mi][2 * kf + 1][3], pah[mi][3], pal[mi][3]);
            }
            #pragma unroll
            for (int nip = 0; nip < 4; nip++) {
                uint32_t vh[4], vl[4];
                const uint32_t off = 2 * (kf * 16 * PQ + nip * 16 + va);
                ldm_x4_t(vh, aVh + off);
                ldm_x4_t(vl, aVl + off);
                #pragma unroll
                for (int mi = 0; mi < 2; mi++)
                    #pragma unroll
                    for (int j = 0; j < 2; j++) {
                        const int ni = nip * 2 + j;
                        mma16816(accO[mi][ni], pah[mi], &vh[2 * j]);
                        mma16816(accO[mi][ni], pah[mi], &vl[2 * j]);
                        mma16816(accO[mi][ni], pal[mi], &vh[2 * j]);
                    }
            }
        }
    }

    // ---- epilogue ----
    float inv[2][2];
    #pragma unroll
    for (int mi = 0; mi < 2; mi++)
        #pragma unroll
        for (int half = 0; half < 2; half++) {
            float l = lrow[mi][half];
            l += __shfl_xor_sync(0xFFFFFFFFu, l, 1);
            l += __shfl_xor_sync(0xFFFFFFFFu, l, 2);
            inv[mi][half] = 1.0f / l;
        }

    #pragma unroll
    for (int mi = 0; mi < 2; mi++)
        #pragma unroll
        for (int ni = 0; ni < 8; ni++)
            #pragma unroll
            for (int half = 0; half < 2; half++) {
                const int row = q0 + wq0 + mi * 16 + (lane >> 2) + half * 8;
                const int col = ni * 8 + (lane & 3) * 2;
                float2 v = make_float2(accO[mi][ni][half * 2] * inv[mi][half],
                                       accO[mi][ni][half * 2 + 1] * inv[mi][half]);
                *(float2*)(g_x + ((size_t)(b * SEQ + row)) * DIM + h * HDIM + col) = v;
            }
}

// ---------------------------------------------------------------------------
// Launch
// ---------------------------------------------------------------------------
extern "C" void kernel_launch(void* const* d_in, const int* in_sizes, int n_in,
                              void* d_out, int out_size)
{
    const float* q    = (const float*)d_in[0];
    const float* k    = (const float*)d_in[1];
    const float* v    = (const float*)d_in[2];
    const int*   mask = (const int*)  d_in[3];
    const float* w_q  = (const float*)d_in[4];
    const float* w_k  = (const float*)d_in[5];
    const float* w_v  = (const float*)d_in[6];
    const float* w_o  = (const float*)d_in[7];
    float* out = (float*)d_out;

    cudaFuncSetAttribute(attn_mma_kernel,
                         cudaFuncAttributeMaxDynamicSharedMemorySize, SMEM_ATTN);

    // 1) Q/K/V projections
    dim3 g1(DIM / 64, NTOK / 128, 3);
    gemm_qkv_tc<<<g1, 256>>>(q, k, v, w_q, w_k, w_v);

    // 2) RoPE on Q and K in-place
    dim3 g2((BHS * SEQ * 32) / 256, 2);
    rope_kernel<<<g2, 256>>>();

    // 3) Tensor-core flash attention
    dim3 g3(SEQ / QB, BHS);
    attn_mma_kernel<<<g3, 128, SMEM_ATTN>>>(mask);

    // 4) Output projection
    dim3 g4(DIM / 64, NTOK / 128);
    gemm_out_tc<<<g4, 256>>>(w_o, out);
}